// round 16
// baseline (speedup 1.0000x reference)
#include <cuda_runtime.h>
#include <math.h>
#include <stdint.h>

#define D_MODEL 1024
#define N_HEADS 16
#define HEAD_DIM 64
#define D_FF 4096
#define ROPE_RANK 16
#define BB 2
#define TT 2048
#define MROWS (BB*TT)   // 4096
#define QKV_N 3072

// ---------------- scratch (static device arrays; no cudaMalloc) ---------------
__device__ float g_qkv[MROWS*QKV_N];
__device__ float g_ctx[MROWS*D_MODEL];
__device__ float g_x[MROWS*D_MODEL];
__device__ float g_x1[MROWS*D_MODEL];
__device__ float g_ff[MROWS*D_FF];
__device__ float g_sinf[TT*512];
__device__ float g_cosf[TT*512];
__device__ float g_w[12*1024*1024];   // tf32-rounded weights
__device__ float g_bqkv[QKV_N];

// ================= helpers ====================================================
__device__ __forceinline__ uint32_t smem_u32(const void* p) {
    uint32_t a;
    asm("{ .reg .u64 t; cvta.to.shared.u64 t, %1; cvt.u32.u64 %0, t; }" : "=r"(a) : "l"(p));
    return a;
}
__device__ __forceinline__ uint32_t f2tf32(float f) {
    uint32_t u;
    asm("cvt.rna.tf32.f32 %0, %1;" : "=r"(u) : "f"(f));
    return u;
}
#define CP_ASYNC16(dst, src) \
    asm volatile("cp.async.cg.shared.global [%0], [%1], 16;" :: "r"(dst), "l"(src) : "memory")
#define CP_COMMIT() asm volatile("cp.async.commit_group;" ::: "memory")
#define CP_WAIT(n)  asm volatile("cp.async.wait_group %0;" :: "n"(n) : "memory")

#define MMA_TF32(d, a, b) \
    asm volatile("mma.sync.aligned.m16n8k8.row.col.f32.tf32.tf32.f32 " \
        "{%0,%1,%2,%3},{%4,%5,%6,%7},{%8,%9},{%0,%1,%2,%3};" \
        : "+f"((d)[0]), "+f"((d)[1]), "+f"((d)[2]), "+f"((d)[3]) \
        : "r"((a)[0]), "r"((a)[1]), "r"((a)[2]), "r"((a)[3]), "r"((b)[0]), "r"((b)[1]))

// ---------------- weight preconvert (fp32 -> tf32-rounded fp32) ---------------
__global__ void cvtw_kernel(const float* __restrict__ src, float* __restrict__ dst, int n4)
{
    int i = blockIdx.x * blockDim.x + threadIdx.x;
    if (i >= n4) return;
    float4 v = *(const float4*)&src[i*4];
    uint4 u = { f2tf32(v.x), f2tf32(v.y), f2tf32(v.z), f2tf32(v.w) };
    *(uint4*)&dst[i*4] = u;
}

// place a 1024-wide weight into a 3072-wide packed matrix at column offset
__global__ void cvtw_place_kernel(const float* __restrict__ src, float* __restrict__ dst,
                                  int n4, int coloff)
{
    int i = blockIdx.x * blockDim.x + threadIdx.x;
    if (i >= n4) return;
    int row = (i*4) >> 10;
    int col = (i*4) & 1023;
    float4 v = *(const float4*)&src[i*4];
    uint4 u = { f2tf32(v.x), f2tf32(v.y), f2tf32(v.z), f2tf32(v.w) };
    *(uint4*)&dst[(size_t)row * QKV_N + coloff + col] = u;
}

__global__ void pack_bias_kernel(const float* __restrict__ bq, const float* __restrict__ bk,
                                 const float* __restrict__ bv, float* __restrict__ dst)
{
    int i = blockIdx.x * blockDim.x + threadIdx.x;
    if (i >= QKV_N) return;
    float v = (i < 1024) ? bq[i] : (i < 2048 ? bk[i-1024] : bv[i-2048]);
    dst[i] = v;
}

// ---------------- tensor-core tf32 GEMM (4-stage cp.async) --------------------
// CTA tile 128x128, BK=16, 128 threads = 4 warps (2x2), warp tile 64x64.
// A is consumed as raw fp32 (HW truncates to tf32); W must be pre-rounded.
#define STAGES 4
#define A_ST 20
#define B_ST 136
#define AS_BYTES (128*A_ST*4)         // 10240
#define BS_BYTES (16*B_ST*4)          // 8704
#define STG_BYTES (AS_BYTES + BS_BYTES)
#define GEMM_SMEM (STAGES*STG_BYTES)  // 75776

__global__ __launch_bounds__(128, 2)
void mma_gemm(const float* __restrict__ A, const float* __restrict__ W,
              const float* __restrict__ bias, const float* __restrict__ resid,
              float* __restrict__ C, int M, int N, int K, int relu)
{
    extern __shared__ char smem[];
    uint32_t sbase = smem_u32(smem);

    int tid = threadIdx.x, lane = tid & 31, wid = tid >> 5;
    int m0 = blockIdx.y * 128, n0 = blockIdx.x * 128;
    int mw = (wid & 1) * 64, nw = (wid >> 1) * 64;
    int gid = lane >> 2, tg = lane & 3;

    float acc[4][8][4];
#pragma unroll
    for (int i = 0; i < 4; i++)
#pragma unroll
        for (int j = 0; j < 8; j++)
#pragma unroll
            for (int c = 0; c < 4; c++) acc[i][j][c] = 0.f;

    // A: one 16-float row per thread (4 x 16B chunks)
    int arow = tid;
    // B: 16 rows x 128 cols; 4 x 16B chunks per thread
    int bk0 = tid >> 5, bc4 = (tid & 31) * 4;
    int T = K >> 4;

    auto issue = [&](int it) {
        int kt = it << 4;
        uint32_t sl = (uint32_t)(it % STAGES) * STG_BYTES;
        const float* Ap = A + (size_t)(m0 + arow) * K + kt;
#pragma unroll
        for (int s_ = 0; s_ < 4; s_++)
            CP_ASYNC16(sbase + sl + (uint32_t)(arow*A_ST + s_*4)*4, Ap + s_*4);
#pragma unroll
        for (int i = 0; i < 4; i++) {
            int k = bk0 + i*4;
            CP_ASYNC16(sbase + sl + AS_BYTES + (uint32_t)(k*B_ST + bc4)*4,
                       &W[(size_t)(kt + k) * N + n0 + bc4]);
        }
    };

    // prologue: STAGES-1 tiles in flight
#pragma unroll
    for (int s = 0; s < STAGES-1; s++) {
        if (s < T) issue(s);
        CP_COMMIT();
    }

    for (int it = 0; it < T; it++) {
        CP_WAIT(STAGES-2);
        __syncthreads();
        int nx = it + STAGES - 1;
        if (nx < T) issue(nx);
        CP_COMMIT();

        uint32_t sl = (uint32_t)(it % STAGES) * STG_BYTES;
        const uint32_t* As = (const uint32_t*)(smem + sl);
        const uint32_t* Bs = (const uint32_t*)(smem + sl + AS_BYTES);
#pragma unroll
        for (int kk = 0; kk < 16; kk += 8) {
            uint32_t af[4][4], bf[8][2];
#pragma unroll
            for (int mi = 0; mi < 4; mi++) {
                int r = mw + mi*16 + gid;
                af[mi][0] = As[r*A_ST + kk + tg];
                af[mi][1] = As[(r+8)*A_ST + kk + tg];
                af[mi][2] = As[r*A_ST + kk + tg + 4];
                af[mi][3] = As[(r+8)*A_ST + kk + tg + 4];
            }
#pragma unroll
            for (int nj = 0; nj < 8; nj++) {
                int c = nw + nj*8 + gid;
                bf[nj][0] = Bs[(kk + tg)*B_ST + c];
                bf[nj][1] = Bs[(kk + tg + 4)*B_ST + c];
            }
#pragma unroll
            for (int mi = 0; mi < 4; mi++)
#pragma unroll
                for (int nj = 0; nj < 8; nj++)
                    MMA_TF32(acc[mi][nj], af[mi], bf[nj]);
        }
    }

    // ---- epilogue ----
#pragma unroll
    for (int mi = 0; mi < 4; mi++) {
#pragma unroll
        for (int nj = 0; nj < 8; nj++) {
            int r = m0 + mw + mi*16 + gid;
            int c = n0 + nw + nj*8 + 2*tg;
            float2 bv = *(const float2*)&bias[c];
#pragma unroll
            for (int h = 0; h < 2; h++) {
                int rr = r + h*8;
                float2 v = { acc[mi][nj][2*h] + bv.x, acc[mi][nj][2*h+1] + bv.y };
                if (resid) {
                    float2 rv = *(const float2*)&resid[(size_t)rr * N + c];
                    v.x += rv.x; v.y += rv.y;
                }
                if (relu) { v.x = fmaxf(v.x, 0.f); v.y = fmaxf(v.y, 0.f); }
                *(float2*)&C[(size_t)rr * N + c] = v;
            }
        }
    }
}

// ---------------- RoPE factor precompute -------------------------------------
__global__ void rope_factors_kernel(const float* __restrict__ A,
                                    const float* __restrict__ Bm,
                                    float* __restrict__ sf, float* __restrict__ cf)
{
    int t = blockIdx.x;
    __shared__ float base[1024];
    __shared__ float tmp[ROPE_RANK];
    __shared__ float wred[8][ROPE_RANK];
    int tid = threadIdx.x;

    for (int j = tid; j < 1024; j += 256) {
        int i = j & 511;
        double theta_d = exp(-log(10000.0) * (double)i / 512.0);
        float theta = (float)theta_d;
        float ang = (float)t * theta;
        base[j] = (j < 512) ? sinf(ang) : cosf(ang);
    }
    __syncthreads();

    float loc[ROPE_RANK];
#pragma unroll
    for (int r = 0; r < ROPE_RANK; r++) loc[r] = 0.f;
    for (int j = tid; j < 1024; j += 256) {
        float bj = base[j];
#pragma unroll
        for (int r = 0; r < ROPE_RANK; r++) loc[r] += bj * A[j*ROPE_RANK + r];
    }
#pragma unroll
    for (int r = 0; r < ROPE_RANK; r++) {
#pragma unroll
        for (int off = 16; off; off >>= 1)
            loc[r] += __shfl_xor_sync(0xffffffffu, loc[r], off);
    }
    int warp = tid >> 5, lane = tid & 31;
    if (lane == 0) {
#pragma unroll
        for (int r = 0; r < ROPE_RANK; r++) wred[warp][r] = loc[r];
    }
    __syncthreads();
    if (tid < ROPE_RANK) {
        float s = 0.f;
#pragma unroll
        for (int w = 0; w < 8; w++) s += wred[w][tid];
        tmp[tid] = s;
    }
    __syncthreads();

    for (int d = tid; d < 1024; d += 256) {
        float s = 0.f;
#pragma unroll
        for (int r = 0; r < ROPE_RANK; r++) s += tmp[r] * Bm[r*1024 + d];
        float val = base[d] + s;
        if (d < 512) sf[t*512 + d]       = val;
        else         cf[t*512 + d - 512] = val;
    }
}

// ---------------- RoPE apply (q,k inside packed qkv) ---------------------------
__global__ void rope_apply_kernel(float* __restrict__ qkv,
                                  const float* __restrict__ sf, const float* __restrict__ cf)
{
    int idx = blockIdx.x * blockDim.x + threadIdx.x;
    if (idx >= MROWS*512) return;
    int p   = idx & 511;
    int row = idx >> 9;
    int t   = row & (TT-1);
    float s = sf[t*512 + p];
    float c = cf[t*512 + p];
    size_t base = (size_t)row*QKV_N + 2*p;
    float qe = qkv[base], qo = qkv[base+1];
    qkv[base]   = qe*c - qo*s;
    qkv[base+1] = qe*s + qo*c;
    float ke = qkv[base+1024], ko = qkv[base+1025];
    qkv[base+1024] = ke*c - ko*s;
    qkv[base+1025] = ke*s + ko*c;
}

// ---------------- Flash attention (tf32 mma.sync, cp.async K/V) ---------------
// 64q x 64k tiles, 128 threads (4 warps x 16 query rows), HEAD_DIM=64.
#define QS_ST 68
#define VS_ST 72
#define KS_FL (64*QS_ST)   // 4352 floats per K stage
#define VS_FL (64*VS_ST)   // 4608 floats per V stage
#define ATTN_SMEM ((2*KS_FL + 2*KS_FL/1*0 + 2*64*QS_ST + 2*VS_FL)*4)
#undef ATTN_SMEM
#define ATTN_SMEM ((64*QS_ST + 64*QS_ST + 2*KS_FL + 2*VS_FL)*4)   // 106496 B

__global__ __launch_bounds__(128)
void attn_mma_kernel(const float* __restrict__ q, const float* __restrict__ k,
                     const float* __restrict__ v, int ld, float* __restrict__ ctx)
{
    extern __shared__ float sm[];
    float* Qs  = sm;                       // 64 x 68
    float* Ps  = Qs + 64*QS_ST;            // 64 x 68
    float* Ks0 = Ps + 64*QS_ST;            // 2 x (64 x 68)
    float* Vs0 = Ks0 + 2*KS_FL;            // 2 x (64 x 72)
    uint32_t ks_u = smem_u32(Ks0);
    uint32_t vs_u = smem_u32(Vs0);

    int tid = threadIdx.x, lane = tid & 31, wid = tid >> 5;
    int gid = lane >> 2, tg = lane & 3;
    int qblk = blockIdx.x, bh = blockIdx.y;
    int b = bh >> 4, h = bh & 15;
    int q0 = qblk * 64;
    size_t rowbase = (size_t)b * TT;
    int colbase = h * HEAD_DIM;
    const float scale = 0.125f;

    // K/V tile issue: 2 threads per row, 8 x 16B chunks each
    int lr = tid >> 1, lc = (tid & 1) * 8;
    auto issue_kv = [&](int kt, int buf) {
        uint32_t kdst = ks_u + (uint32_t)(buf*KS_FL + lr*QS_ST)*4;
        uint32_t vdst = vs_u + (uint32_t)(buf*VS_FL + lr*VS_ST)*4;
        const float* kp = &k[(rowbase + kt + lr)*ld + colbase];
        const float* vp = &v[(rowbase + kt + lr)*ld + colbase];
#pragma unroll
        for (int j = 0; j < 8; j++) {
            CP_ASYNC16(kdst + (lc + j)*16, kp + (lc + j)*4);
            CP_ASYNC16(vdst + (lc + j)*16, vp + (lc + j)*4);
        }
    };

    // load Q tile (scaled, tf32-rounded)
    for (int i = tid; i < 64*16; i += 128) {
        int r = i >> 4, c4 = (i & 15) * 4;
        float4 val = *(const float4*)&q[(rowbase + q0 + r)*ld + colbase + c4];
        uint4 u = { f2tf32(val.x*scale), f2tf32(val.y*scale),
                    f2tf32(val.z*scale), f2tf32(val.w*scale) };
        *(uint4*)&Qs[r*QS_ST + c4] = u;
    }

    issue_kv(0, 0);
    CP_COMMIT();

    int qw = wid * 16;
    int r0 = qw + gid, r1 = r0 + 8;

    float m_i[2] = { -1e30f, -1e30f };
    float l_i[2] = { 0.f, 0.f };
    float oacc[8][4];
#pragma unroll
    for (int nj = 0; nj < 8; nj++)
#pragma unroll
        for (int c = 0; c < 4; c++) oacc[nj][c] = 0.f;

    for (int ti = 0; ti < TT/64; ti++) {
        CP_WAIT(0);
        __syncthreads();
        if (ti + 1 < TT/64) { issue_kv((ti+1)*64, (ti+1) & 1); CP_COMMIT(); }

        const float* Ks = Ks0 + (ti & 1) * KS_FL;
        const float* Vs = Vs0 + (ti & 1) * VS_FL;

        // ---- S = Q K^T ----
        float sacc[8][4];
#pragma unroll
        for (int nj = 0; nj < 8; nj++)
#pragma unroll
            for (int c = 0; c < 4; c++) sacc[nj][c] = 0.f;
#pragma unroll
        for (int kk = 0; kk < 64; kk += 8) {
            uint32_t af[4];
            af[0] = __float_as_uint(Qs[r0*QS_ST + kk + tg]);
            af[1] = __float_as_uint(Qs[r1*QS_ST + kk + tg]);
            af[2] = __float_as_uint(Qs[r0*QS_ST + kk + tg + 4]);
            af[3] = __float_as_uint(Qs[r1*QS_ST + kk + tg + 4]);
#pragma unroll
            for (int nj = 0; nj < 8; nj++) {
                uint32_t bf[2];
                bf[0] = __float_as_uint(Ks[(nj*8 + gid)*QS_ST + kk + tg]);
                bf[1] = __float_as_uint(Ks[(nj*8 + gid)*QS_ST + kk + tg + 4]);
                MMA_TF32(sacc[nj], af, bf);
            }
        }

        // ---- online softmax ----
#pragma unroll
        for (int rh = 0; rh < 2; rh++) {
            float tm = -1e30f;
#pragma unroll
            for (int nj = 0; nj < 8; nj++)
                tm = fmaxf(tm, fmaxf(sacc[nj][2*rh], sacc[nj][2*rh+1]));
            tm = fmaxf(tm, __shfl_xor_sync(0xffffffffu, tm, 1));
            tm = fmaxf(tm, __shfl_xor_sync(0xffffffffu, tm, 2));
            float m_new = fmaxf(m_i[rh], tm);
            float corr  = __expf(m_i[rh] - m_new);
            float rs = 0.f;
            int row = rh ? r1 : r0;
#pragma unroll
            for (int nj = 0; nj < 8; nj++) {
                float p0 = __expf(sacc[nj][2*rh]   - m_new);
                float p1 = __expf(sacc[nj][2*rh+1] - m_new);
                rs += p0 + p1;
                uint2 pu = { f2tf32(p0), f2tf32(p1) };
                *(uint2*)&Ps[row*QS_ST + nj*8 + 2*tg] = pu;
                oacc[nj][2*rh]   *= corr;
                oacc[nj][2*rh+1] *= corr;
            }
            rs += __shfl_xor_sync(0xffffffffu, rs, 1);
            rs += __shfl_xor_sync(0xffffffffu, rs, 2);
            l_i[rh] = l_i[rh]*corr + rs;
            m_i[rh] = m_new;
        }
        __syncwarp();

        // ---- O += P V ----
#pragma unroll
        for (int kk = 0; kk < 64; kk += 8) {
            uint32_t af[4];
            af[0] = __float_as_uint(Ps[r0*QS_ST + kk + tg]);
            af[1] = __float_as_uint(Ps[r1*QS_ST + kk + tg]);
            af[2] = __float_as_uint(Ps[r0*QS_ST + kk + tg + 4]);
            af[3] = __float_as_uint(Ps[r1*QS_ST + kk + tg + 4]);
#pragma unroll
            for (int nj = 0; nj < 8; nj++) {
                uint32_t bf[2];
                bf[0] = __float_as_uint(Vs[(kk + tg)*VS_ST + nj*8 + gid]);
                bf[1] = __float_as_uint(Vs[(kk + tg + 4)*VS_ST + nj*8 + gid]);
                MMA_TF32(oacc[nj], af, bf);
            }
        }
    }

    float inv0 = 1.f / l_i[0], inv1 = 1.f / l_i[1];
#pragma unroll
    for (int nj = 0; nj < 8; nj++) {
        int c = colbase + nj*8 + 2*tg;
        float2 o0 = { oacc[nj][0]*inv0, oacc[nj][1]*inv0 };
        float2 o1 = { oacc[nj][2]*inv1, oacc[nj][3]*inv1 };
        *(float2*)&ctx[(rowbase + q0 + r0)*D_MODEL + c] = o0;
        *(float2*)&ctx[(rowbase + q0 + r1)*D_MODEL + c] = o1;
    }
}

// ---------------- LayerNorm ---------------------------------------------------
__global__ __launch_bounds__(256)
void layernorm_kernel(const float* __restrict__ x, const float* __restrict__ g,
                      const float* __restrict__ bvec, float* __restrict__ out)
{
    int row = blockIdx.x;
    int tid = threadIdx.x;
    const float* xr = x + (size_t)row * D_MODEL;
    float4 v = *(const float4*)&xr[tid*4];
    float s  = v.x + v.y + v.z + v.w;
    float s2 = v.x*v.x + v.y*v.y + v.z*v.z + v.w*v.w;
#pragma unroll
    for (int off = 16; off; off >>= 1) {
        s  += __shfl_xor_sync(0xffffffffu, s,  off);
        s2 += __shfl_xor_sync(0xffffffffu, s2, off);
    }
    __shared__ float ws[8], ws2[8];
    __shared__ float smu, sinv;
    int warp = tid >> 5;
    if ((tid & 31) == 0) { ws[warp] = s; ws2[warp] = s2; }
    __syncthreads();
    if (tid == 0) {
        float a = 0.f, b2 = 0.f;
#pragma unroll
        for (int w = 0; w < 8; w++) { a += ws[w]; b2 += ws2[w]; }
        float mu  = a * (1.f/1024.f);
        float var = b2 * (1.f/1024.f) - mu*mu;
        smu = mu;
        sinv = rsqrtf(var + 1e-5f);
    }
    __syncthreads();
    float mu = smu, inv = sinv;
    float4 gg  = *(const float4*)&g[tid*4];
    float4 bb4 = *(const float4*)&bvec[tid*4];
    float4 o;
    o.x = (v.x - mu)*inv*gg.x + bb4.x;
    o.y = (v.y - mu)*inv*gg.y + bb4.y;
    o.z = (v.z - mu)*inv*gg.z + bb4.z;
    o.w = (v.w - mu)*inv*gg.w + bb4.w;
    *(float4*)&out[(size_t)row * D_MODEL + tid*4] = o;
}

// ---------------- launch ------------------------------------------------------
extern "C" void kernel_launch(void* const* d_in, const int* in_sizes, int n_in,
                              void* d_out, int out_size)
{
    const float* tgt  = (const float*)d_in[0];
    const float* Wq   = (const float*)d_in[1];
    const float* bq   = (const float*)d_in[2];
    const float* Wk   = (const float*)d_in[3];
    const float* bk   = (const float*)d_in[4];
    const float* Wv   = (const float*)d_in[5];
    const float* bv   = (const float*)d_in[6];
    const float* Wo   = (const float*)d_in[7];
    const float* bo   = (const float*)d_in[8];
    const float* W1   = (const float*)d_in[9];
    const float* b1   = (const float*)d_in[10];
    const float* W2   = (const float*)d_in[11];
    const float* b2   = (const float*)d_in[12];
    const float* ln1g = (const float*)d_in[13];
    const float* ln1b = (const float*)d_in[14];
    const float* ln2g = (const float*)d_in[15];
    const float* ln2b = (const float*)d_in[16];
    const float* ropeA = (const float*)d_in[17];
    const float* ropeB = (const float*)d_in[18];
    float* out = (float*)d_out;

    float *pqkv, *pctx, *px, *px1, *pff, *psin, *pcos, *pw, *pbqkv;
    cudaGetSymbolAddress((void**)&pqkv, g_qkv);
    cudaGetSymbolAddress((void**)&pctx, g_ctx);
    cudaGetSymbolAddress((void**)&px,   g_x);
    cudaGetSymbolAddress((void**)&px1,  g_x1);
    cudaGetSymbolAddress((void**)&pff,  g_ff);
    cudaGetSymbolAddress((void**)&psin, g_sinf);
    cudaGetSymbolAddress((void**)&pcos, g_cosf);
    cudaGetSymbolAddress((void**)&pw,   g_w);
    cudaGetSymbolAddress((void**)&pbqkv, g_bqkv);

    float* tWqkv = pw;                 // 1024 x 3072
    float* tWo   = pw + 3*1048576;
    float* tW1   = pw + 4*1048576;
    float* tW2   = pw + 8*1048576;

    cudaFuncSetAttribute(attn_mma_kernel,
                         cudaFuncAttributeMaxDynamicSharedMemorySize, ATTN_SMEM);
    cudaFuncSetAttribute(mma_gemm,
                         cudaFuncAttributeMaxDynamicSharedMemorySize, GEMM_SMEM);

    // 0. weight preconvert / pack
    cvtw_place_kernel<<<1048576/4/256, 256>>>(Wq, tWqkv, 1048576/4, 0);
    cvtw_place_kernel<<<1048576/4/256, 256>>>(Wk, tWqkv, 1048576/4, 1024);
    cvtw_place_kernel<<<1048576/4/256, 256>>>(Wv, tWqkv, 1048576/4, 2048);
    cvtw_kernel<<<1048576/4/256, 256>>>(Wo, tWo, 1048576/4);
    cvtw_kernel<<<4194304/4/256, 256>>>(W1, tW1, 4194304/4);
    cvtw_kernel<<<4194304/4/256, 256>>>(W2, tW2, 4194304/4);
    pack_bias_kernel<<<QKV_N/256, 256>>>(bq, bk, bv, pbqkv);

    // 1. RoPE factors
    rope_factors_kernel<<<TT, 256>>>(ropeA, ropeB, psin, pcos);

    // 2. fused QKV projection
    dim3 gqkv(QKV_N/128, MROWS/128);
    mma_gemm<<<gqkv, 128, GEMM_SMEM>>>(tgt, tWqkv, pbqkv, nullptr, pqkv,
                                       MROWS, QKV_N, D_MODEL, 0);

    // 3. RoPE on q, k (inside packed qkv)
    rope_apply_kernel<<<(MROWS*512)/256, 256>>>(pqkv, psin, pcos);

    // 4. Attention (tensor core, cp.async double-buffered K/V)
    dim3 ga(TT/64, BB*N_HEADS);
    attn_mma_kernel<<<ga, 128, ATTN_SMEM>>>(pqkv, pqkv + 1024, pqkv + 2048,
                                            QKV_N, pctx);

    // 5. Output projection + residual
    dim3 g1024(D_MODEL/128, MROWS/128);
    mma_gemm<<<g1024, 128, GEMM_SMEM>>>(pctx, tWo, bo, tgt, px, MROWS, D_MODEL, D_MODEL, 0);

    // 6. LN1
    layernorm_kernel<<<MROWS, 256>>>(px, ln1g, ln1b, px1);

    // 7. FFN
    dim3 gff1(D_FF/128, MROWS/128);
    mma_gemm<<<gff1, 128, GEMM_SMEM>>>(px1, tW1, b1, nullptr, pff, MROWS, D_FF, D_MODEL, 1);
    mma_gemm<<<g1024, 128, GEMM_SMEM>>>(pff, tW2, b2, px1, px, MROWS, D_MODEL, D_FF, 0);

    // 8. LN2 -> output
    layernorm_kernel<<<MROWS, 256>>>(px, ln2g, ln2b, out);
}

// round 17
// speedup vs baseline: 1.2445x; 1.2445x over previous
#include <cuda_runtime.h>
#include <cuda_fp16.h>
#include <math.h>
#include <stdint.h>

#define D_MODEL 1024
#define N_HEADS 16
#define HEAD_DIM 64
#define D_FF 4096
#define ROPE_RANK 16
#define BB 2
#define TT 2048
#define MROWS (BB*TT)   // 4096
#define QKV_N 3072

// ---------------- scratch (static device arrays; no cudaMalloc) ---------------
__device__ float g_qkv[MROWS*QKV_N];
__device__ float g_ctx[MROWS*D_MODEL];
__device__ float g_x[MROWS*D_MODEL];
__device__ float g_x1[MROWS*D_MODEL];
__device__ float g_ff[MROWS*D_FF];
__device__ float g_sinf[TT*512];
__device__ float g_cosf[TT*512];
__device__ float g_w[12*1024*1024];   // reused as fp16 [N][K] transposed weights
__device__ float g_bqkv[QKV_N];

// ================= helpers ====================================================
__device__ __forceinline__ uint32_t smem_u32(const void* p) {
    uint32_t a;
    asm("{ .reg .u64 t; cvta.to.shared.u64 t, %1; cvt.u32.u64 %0, t; }" : "=r"(a) : "l"(p));
    return a;
}
__device__ __forceinline__ uint32_t f2tf32(float f) {
    uint32_t u;
    asm("cvt.rna.tf32.f32 %0, %1;" : "=r"(u) : "f"(f));
    return u;
}
__device__ __forceinline__ uint32_t packh2(float lo, float hi) {
    __half2 h = __floats2half2_rn(lo, hi);
    return *(uint32_t*)&h;
}
#define CP_ASYNC16(dst, src) \
    asm volatile("cp.async.cg.shared.global [%0], [%1], 16;" :: "r"(dst), "l"(src) : "memory")
#define CP_COMMIT() asm volatile("cp.async.commit_group;" ::: "memory")
#define CP_WAIT(n)  asm volatile("cp.async.wait_group %0;" :: "n"(n) : "memory")

#define MMA_TF32(d, a, b) \
    asm volatile("mma.sync.aligned.m16n8k8.row.col.f32.tf32.tf32.f32 " \
        "{%0,%1,%2,%3},{%4,%5,%6,%7},{%8,%9},{%0,%1,%2,%3};" \
        : "+f"((d)[0]), "+f"((d)[1]), "+f"((d)[2]), "+f"((d)[3]) \
        : "r"((a)[0]), "r"((a)[1]), "r"((a)[2]), "r"((a)[3]), "r"((b)[0]), "r"((b)[1]))

#define MMA_F16(d, a, b) \
    asm volatile("mma.sync.aligned.m16n8k16.row.col.f32.f16.f16.f32 " \
        "{%0,%1,%2,%3},{%4,%5,%6,%7},{%8,%9},{%0,%1,%2,%3};" \
        : "+f"((d)[0]), "+f"((d)[1]), "+f"((d)[2]), "+f"((d)[3]) \
        : "r"((a)[0]), "r"((a)[1]), "r"((a)[2]), "r"((a)[3]), "r"((b)[0]), "r"((b)[1]))

// ---------------- weight transpose-convert: fp32[K][N] -> fp16[N][K] ----------
__global__ void cvtw_t_kernel(const float* __restrict__ src, __half* __restrict__ dst,
                              int K, int N)
{
    __shared__ float tile[32][33];
    int n0 = blockIdx.x * 32, k0 = blockIdx.y * 32;
    int tx = threadIdx.x, ty = threadIdx.y;   // 32 x 8
#pragma unroll
    for (int i = 0; i < 32; i += 8)
        tile[ty + i][tx] = src[(size_t)(k0 + ty + i) * N + n0 + tx];
    __syncthreads();
#pragma unroll
    for (int i = 0; i < 32; i += 8)
        dst[(size_t)(n0 + ty + i) * K + k0 + tx] = __float2half_rn(tile[tx][ty + i]);
}

__global__ void pack_bias_kernel(const float* __restrict__ bq, const float* __restrict__ bk,
                                 const float* __restrict__ bv, float* __restrict__ dst)
{
    int i = blockIdx.x * blockDim.x + threadIdx.x;
    if (i >= QKV_N) return;
    float v = (i < 1024) ? bq[i] : (i < 2048 ? bk[i-1024] : bv[i-2048]);
    dst[i] = v;
}

// ---------------- tensor-core fp16 GEMM (fp32 accum) --------------------------
// C[M,N] = A[M,K] @ Wt[N,K]^T (+bias,+resid,relu). CTA 128x128, BK=32,
// 128 threads = 4 warps (2x2), warp tile 64x64. Wt is fp16 [N][K] row-major.
#define T_ST 20                        // u32 pitch per 128-row tile (16 data + 4 pad)
#define TILE_B (128*T_ST*4)            // 10240 B (A or B half-tile)
#define HSTAGE_B (2*TILE_B)            // 20480
#define GEMM_SMEM (2*HSTAGE_B)         // 40960

__global__ __launch_bounds__(128, 2)
void hgemm(const float* __restrict__ A, const __half* __restrict__ Wt,
           const float* __restrict__ bias, const float* __restrict__ resid,
           float* __restrict__ C, int M, int N, int K, int relu)
{
    extern __shared__ char smem[];
    uint32_t sbase = smem_u32(smem);

    int tid = threadIdx.x, lane = tid & 31, wid = tid >> 5;
    int m0 = blockIdx.y * 128, n0 = blockIdx.x * 128;
    int mw = (wid & 1) * 64, nw = (wid >> 1) * 64;
    int gid = lane >> 2, tg = lane & 3;

    float acc[4][8][4];
#pragma unroll
    for (int i = 0; i < 4; i++)
#pragma unroll
        for (int j = 0; j < 8; j++)
#pragma unroll
            for (int c = 0; c < 4; c++) acc[i][j][c] = 0.f;

    // A: 4 threads per row, 8 floats each; rows ar+32i
    int ar = tid >> 2, ac = (tid & 3) * 8;
    int T = K >> 5;

    float4 aReg[4][2];
    const __half* Wrow = Wt + (size_t)(n0 + tid) * K;

    // ---- prologue: stage 0 ----
#pragma unroll
    for (int i = 0; i < 4; i++) {
        const float* Ap = &A[(size_t)(m0 + ar + i*32) * K + ac];
        aReg[i][0] = *(const float4*)Ap;
        aReg[i][1] = *(const float4*)(Ap + 4);
    }
#pragma unroll
    for (int j = 0; j < 4; j++)
        CP_ASYNC16(sbase + TILE_B + (uint32_t)tid*T_ST*4 + j*16,
                   (const char*)(Wrow + j*8));
    CP_COMMIT();
#pragma unroll
    for (int i = 0; i < 4; i++) {
        uint4 u = { packh2(aReg[i][0].x, aReg[i][0].y), packh2(aReg[i][0].z, aReg[i][0].w),
                    packh2(aReg[i][1].x, aReg[i][1].y), packh2(aReg[i][1].z, aReg[i][1].w) };
        *(uint4*)(smem + ((ar + i*32)*T_ST + (tid & 3)*4)*4) = u;
    }

    for (int it = 0; it < T; it++) {
        int s = it & 1;
        uint32_t sl = s ? HSTAGE_B : 0;
        uint32_t sn = s ? 0 : HSTAGE_B;
        bool has_next = (it + 1 < T);
        if (has_next) {
            int kt = (it + 1) << 5;
#pragma unroll
            for (int i = 0; i < 4; i++) {
                const float* Ap = &A[(size_t)(m0 + ar + i*32) * K + kt + ac];
                aReg[i][0] = *(const float4*)Ap;
                aReg[i][1] = *(const float4*)(Ap + 4);
            }
#pragma unroll
            for (int j = 0; j < 4; j++)
                CP_ASYNC16(sbase + sn + TILE_B + (uint32_t)tid*T_ST*4 + j*16,
                           (const char*)(Wrow + kt + j*8));
            CP_COMMIT();
            CP_WAIT(1);
        } else {
            CP_WAIT(0);
        }
        __syncthreads();

        const uint32_t* As = (const uint32_t*)(smem + sl);
        const uint32_t* Bs = (const uint32_t*)(smem + sl + TILE_B);
#pragma unroll
        for (int c = 0; c < 2; c++) {      // two k16 chunks
            int base = c * 8;
            uint32_t af[4][4], bf[8][2];
#pragma unroll
            for (int mi = 0; mi < 4; mi++) {
                int r = mw + mi*16 + gid;
                af[mi][0] = As[r*T_ST + base + tg];
                af[mi][1] = As[(r+8)*T_ST + base + tg];
                af[mi][2] = As[r*T_ST + base + 4 + tg];
                af[mi][3] = As[(r+8)*T_ST + base + 4 + tg];
            }
#pragma unroll
            for (int nj = 0; nj < 8; nj++) {
                int cn = nw + nj*8 + gid;
                bf[nj][0] = Bs[cn*T_ST + base + tg];
                bf[nj][1] = Bs[cn*T_ST + base + 4 + tg];
            }
#pragma unroll
            for (int mi = 0; mi < 4; mi++)
#pragma unroll
                for (int nj = 0; nj < 8; nj++)
                    MMA_F16(acc[mi][nj], af[mi], bf[nj]);
        }

        if (has_next) {
#pragma unroll
            for (int i = 0; i < 4; i++) {
                uint4 u = { packh2(aReg[i][0].x, aReg[i][0].y), packh2(aReg[i][0].z, aReg[i][0].w),
                            packh2(aReg[i][1].x, aReg[i][1].y), packh2(aReg[i][1].z, aReg[i][1].w) };
                *(uint4*)(smem + sn + ((ar + i*32)*T_ST + (tid & 3)*4)*4) = u;
            }
        }
        __syncthreads();
    }

    // ---- epilogue ----
#pragma unroll
    for (int mi = 0; mi < 4; mi++) {
#pragma unroll
        for (int nj = 0; nj < 8; nj++) {
            int r = m0 + mw + mi*16 + gid;
            int c = n0 + nw + nj*8 + 2*tg;
            float2 bv = *(const float2*)&bias[c];
#pragma unroll
            for (int h = 0; h < 2; h++) {
                int rr = r + h*8;
                float2 v = { acc[mi][nj][2*h] + bv.x, acc[mi][nj][2*h+1] + bv.y };
                if (resid) {
                    float2 rv = *(const float2*)&resid[(size_t)rr * N + c];
                    v.x += rv.x; v.y += rv.y;
                }
                if (relu) { v.x = fmaxf(v.x, 0.f); v.y = fmaxf(v.y, 0.f); }
                *(float2*)&C[(size_t)rr * N + c] = v;
            }
        }
    }
}

// ---------------- RoPE factor precompute -------------------------------------
__global__ void rope_factors_kernel(const float* __restrict__ A,
                                    const float* __restrict__ Bm,
                                    float* __restrict__ sf, float* __restrict__ cf)
{
    int t = blockIdx.x;
    __shared__ float base[1024];
    __shared__ float tmp[ROPE_RANK];
    __shared__ float wred[8][ROPE_RANK];
    int tid = threadIdx.x;

    for (int j = tid; j < 1024; j += 256) {
        int i = j & 511;
        double theta_d = exp(-log(10000.0) * (double)i / 512.0);
        float theta = (float)theta_d;
        float ang = (float)t * theta;
        base[j] = (j < 512) ? sinf(ang) : cosf(ang);
    }
    __syncthreads();

    float loc[ROPE_RANK];
#pragma unroll
    for (int r = 0; r < ROPE_RANK; r++) loc[r] = 0.f;
    for (int j = tid; j < 1024; j += 256) {
        float bj = base[j];
#pragma unroll
        for (int r = 0; r < ROPE_RANK; r++) loc[r] += bj * A[j*ROPE_RANK + r];
    }
#pragma unroll
    for (int r = 0; r < ROPE_RANK; r++) {
#pragma unroll
        for (int off = 16; off; off >>= 1)
            loc[r] += __shfl_xor_sync(0xffffffffu, loc[r], off);
    }
    int warp = tid >> 5, lane = tid & 31;
    if (lane == 0) {
#pragma unroll
        for (int r = 0; r < ROPE_RANK; r++) wred[warp][r] = loc[r];
    }
    __syncthreads();
    if (tid < ROPE_RANK) {
        float s = 0.f;
#pragma unroll
        for (int w = 0; w < 8; w++) s += wred[w][tid];
        tmp[tid] = s;
    }
    __syncthreads();

    for (int d = tid; d < 1024; d += 256) {
        float s = 0.f;
#pragma unroll
        for (int r = 0; r < ROPE_RANK; r++) s += tmp[r] * Bm[r*1024 + d];
        float val = base[d] + s;
        if (d < 512) sf[t*512 + d]       = val;
        else         cf[t*512 + d - 512] = val;
    }
}

// ---------------- RoPE apply (q,k inside packed qkv) ---------------------------
__global__ void rope_apply_kernel(float* __restrict__ qkv,
                                  const float* __restrict__ sf, const float* __restrict__ cf)
{
    int idx = blockIdx.x * blockDim.x + threadIdx.x;
    if (idx >= MROWS*512) return;
    int p   = idx & 511;
    int row = idx >> 9;
    int t   = row & (TT-1);
    float s = sf[t*512 + p];
    float c = cf[t*512 + p];
    size_t base = (size_t)row*QKV_N + 2*p;
    float qe = qkv[base], qo = qkv[base+1];
    qkv[base]   = qe*c - qo*s;
    qkv[base+1] = qe*s + qo*c;
    float ke = qkv[base+1024], ko = qkv[base+1025];
    qkv[base+1024] = ke*c - ko*s;
    qkv[base+1025] = ke*s + ko*c;
}

// ---------------- Flash attention (tf32 mma.sync) — R10 proven version --------
#define QS_ST 68
#define VS_ST 72
#define ATTN_SMEM ((3*64*QS_ST + 64*VS_ST)*4)   // 70656 B

__global__ __launch_bounds__(128)
void attn_mma_kernel(const float* __restrict__ q, const float* __restrict__ k,
                     const float* __restrict__ v, int ld, float* __restrict__ ctx)
{
    extern __shared__ float sm[];
    float* Qs = sm;
    float* Ks = Qs + 64*QS_ST;
    float* Ps = Ks + 64*QS_ST;
    float* Vs = Ps + 64*QS_ST;

    int tid = threadIdx.x, lane = tid & 31, wid = tid >> 5;
    int gid = lane >> 2, tg = lane & 3;
    int qblk = blockIdx.x, bh = blockIdx.y;
    int b = bh >> 4, h = bh & 15;
    int q0 = qblk * 64;
    size_t rowbase = (size_t)b * TT;
    int colbase = h * HEAD_DIM;
    const float scale = 0.125f;

    for (int i = tid; i < 64*16; i += 128) {
        int r = i >> 4, c4 = (i & 15) * 4;
        float4 val = *(const float4*)&q[(rowbase + q0 + r)*ld + colbase + c4];
        uint4 u = { f2tf32(val.x*scale), f2tf32(val.y*scale),
                    f2tf32(val.z*scale), f2tf32(val.w*scale) };
        *(uint4*)&Qs[r*QS_ST + c4] = u;
    }

    int qw = wid * 16;
    int r0 = qw + gid, r1 = r0 + 8;

    float m_i[2] = { -1e30f, -1e30f };
    float l_i[2] = { 0.f, 0.f };
    float oacc[8][4];
#pragma unroll
    for (int nj = 0; nj < 8; nj++)
#pragma unroll
        for (int c = 0; c < 4; c++) oacc[nj][c] = 0.f;

    for (int kt = 0; kt < TT; kt += 64) {
        __syncthreads();
        for (int i = tid; i < 64*16; i += 128) {
            int r = i >> 4, c4 = (i & 15) * 4;
            float4 kv = *(const float4*)&k[(rowbase + kt + r)*ld + colbase + c4];
            uint4 uk = { f2tf32(kv.x), f2tf32(kv.y), f2tf32(kv.z), f2tf32(kv.w) };
            *(uint4*)&Ks[r*QS_ST + c4] = uk;
            float4 vv = *(const float4*)&v[(rowbase + kt + r)*ld + colbase + c4];
            uint4 uv = { f2tf32(vv.x), f2tf32(vv.y), f2tf32(vv.z), f2tf32(vv.w) };
            *(uint4*)&Vs[r*VS_ST + c4] = uv;
        }
        __syncthreads();

        float sacc[8][4];
#pragma unroll
        for (int nj = 0; nj < 8; nj++)
#pragma unroll
            for (int c = 0; c < 4; c++) sacc[nj][c] = 0.f;
#pragma unroll
        for (int kk = 0; kk < 64; kk += 8) {
            uint32_t af[4];
            af[0] = __float_as_uint(Qs[r0*QS_ST + kk + tg]);
            af[1] = __float_as_uint(Qs[r1*QS_ST + kk + tg]);
            af[2] = __float_as_uint(Qs[r0*QS_ST + kk + tg + 4]);
            af[3] = __float_as_uint(Qs[r1*QS_ST + kk + tg + 4]);
#pragma unroll
            for (int nj = 0; nj < 8; nj++) {
                uint32_t bf[2];
                bf[0] = __float_as_uint(Ks[(nj*8 + gid)*QS_ST + kk + tg]);
                bf[1] = __float_as_uint(Ks[(nj*8 + gid)*QS_ST + kk + tg + 4]);
                MMA_TF32(sacc[nj], af, bf);
            }
        }

#pragma unroll
        for (int rh = 0; rh < 2; rh++) {
            float tm = -1e30f;
#pragma unroll
            for (int nj = 0; nj < 8; nj++)
                tm = fmaxf(tm, fmaxf(sacc[nj][2*rh], sacc[nj][2*rh+1]));
            tm = fmaxf(tm, __shfl_xor_sync(0xffffffffu, tm, 1));
            tm = fmaxf(tm, __shfl_xor_sync(0xffffffffu, tm, 2));
            float m_new = fmaxf(m_i[rh], tm);
            float corr  = __expf(m_i[rh] - m_new);
            float rs = 0.f;
            int row = rh ? r1 : r0;
#pragma unroll
            for (int nj = 0; nj < 8; nj++) {
                float p0 = __expf(sacc[nj][2*rh]   - m_new);
                float p1 = __expf(sacc[nj][2*rh+1] - m_new);
                rs += p0 + p1;
                uint2 pu = { f2tf32(p0), f2tf32(p1) };
                *(uint2*)&Ps[row*QS_ST + nj*8 + 2*tg] = pu;
                oacc[nj][2*rh]   *= corr;
                oacc[nj][2*rh+1] *= corr;
            }
            rs += __shfl_xor_sync(0xffffffffu, rs, 1);
            rs += __shfl_xor_sync(0xffffffffu, rs, 2);
            l_i[rh] = l_i[rh]*corr + rs;
            m_i[rh] = m_new;
        }
        __syncwarp();

#pragma unroll
        for (int kk = 0; kk < 64; kk += 8) {
            uint32_t af[4];
            af[0] = __float_as_uint(Ps[r0*QS_ST + kk + tg]);
            af[1] = __float_as_uint(Ps[r1*QS_ST + kk + tg]);
            af[2] = __float_as_uint(Ps[r0*QS_ST + kk + tg + 4]);
            af[3] = __float_as_uint(Ps[r1*QS_ST + kk + tg + 4]);
#pragma unroll
            for (int nj = 0; nj < 8; nj++) {
                uint32_t bf[2];
                bf[0] = __float_as_uint(Vs[(kk + tg)*VS_ST + nj*8 + gid]);
                bf[1] = __float_as_uint(Vs[(kk + tg + 4)*VS_ST + nj*8 + gid]);
                MMA_TF32(oacc[nj], af, bf);
            }
        }
    }

    float inv0 = 1.f / l_i[0], inv1 = 1.f / l_i[1];
#pragma unroll
    for (int nj = 0; nj < 8; nj++) {
        int c = colbase + nj*8 + 2*tg;
        float2 o0 = { oacc[nj][0]*inv0, oacc[nj][1]*inv0 };
        float2 o1 = { oacc[nj][2]*inv1, oacc[nj][3]*inv1 };
        *(float2*)&ctx[(rowbase + q0 + r0)*D_MODEL + c] = o0;
        *(float2*)&ctx[(rowbase + q0 + r1)*D_MODEL + c] = o1;
    }
}

// ---------------- LayerNorm ---------------------------------------------------
__global__ __launch_bounds__(256)
void layernorm_kernel(const float* __restrict__ x, const float* __restrict__ g,
                      const float* __restrict__ bvec, float* __restrict__ out)
{
    int row = blockIdx.x;
    int tid = threadIdx.x;
    const float* xr = x + (size_t)row * D_MODEL;
    float4 v = *(const float4*)&xr[tid*4];
    float s  = v.x + v.y + v.z + v.w;
    float s2 = v.x*v.x + v.y*v.y + v.z*v.z + v.w*v.w;
#pragma unroll
    for (int off = 16; off; off >>= 1) {
        s  += __shfl_xor_sync(0xffffffffu, s,  off);
        s2 += __shfl_xor_sync(0xffffffffu, s2, off);
    }
    __shared__ float ws[8], ws2[8];
    __shared__ float smu, sinv;
    int warp = tid >> 5;
    if ((tid & 31) == 0) { ws[warp] = s; ws2[warp] = s2; }
    __syncthreads();
    if (tid == 0) {
        float a = 0.f, b2 = 0.f;
#pragma unroll
        for (int w = 0; w < 8; w++) { a += ws[w]; b2 += ws2[w]; }
        float mu  = a * (1.f/1024.f);
        float var = b2 * (1.f/1024.f) - mu*mu;
        smu = mu;
        sinv = rsqrtf(var + 1e-5f);
    }
    __syncthreads();
    float mu = smu, inv = sinv;
    float4 gg  = *(const float4*)&g[tid*4];
    float4 bb4 = *(const float4*)&bvec[tid*4];
    float4 o;
    o.x = (v.x - mu)*inv*gg.x + bb4.x;
    o.y = (v.y - mu)*inv*gg.y + bb4.y;
    o.z = (v.z - mu)*inv*gg.z + bb4.z;
    o.w = (v.w - mu)*inv*gg.w + bb4.w;
    *(float4*)&out[(size_t)row * D_MODEL + tid*4] = o;
}

// ---------------- launch ------------------------------------------------------
extern "C" void kernel_launch(void* const* d_in, const int* in_sizes, int n_in,
                              void* d_out, int out_size)
{
    const float* tgt  = (const float*)d_in[0];
    const float* Wq   = (const float*)d_in[1];
    const float* bq   = (const float*)d_in[2];
    const float* Wk   = (const float*)d_in[3];
    const float* bk   = (const float*)d_in[4];
    const float* Wv   = (const float*)d_in[5];
    const float* bv   = (const float*)d_in[6];
    const float* Wo   = (const float*)d_in[7];
    const float* bo   = (const float*)d_in[8];
    const float* W1   = (const float*)d_in[9];
    const float* b1   = (const float*)d_in[10];
    const float* W2   = (const float*)d_in[11];
    const float* b2   = (const float*)d_in[12];
    const float* ln1g = (const float*)d_in[13];
    const float* ln1b = (const float*)d_in[14];
    const float* ln2g = (const float*)d_in[15];
    const float* ln2b = (const float*)d_in[16];
    const float* ropeA = (const float*)d_in[17];
    const float* ropeB = (const float*)d_in[18];
    float* out = (float*)d_out;

    float *pqkv, *pctx, *px, *px1, *pff, *psin, *pcos, *pw, *pbqkv;
    cudaGetSymbolAddress((void**)&pqkv, g_qkv);
    cudaGetSymbolAddress((void**)&pctx, g_ctx);
    cudaGetSymbolAddress((void**)&px,   g_x);
    cudaGetSymbolAddress((void**)&px1,  g_x1);
    cudaGetSymbolAddress((void**)&pff,  g_ff);
    cudaGetSymbolAddress((void**)&psin, g_sinf);
    cudaGetSymbolAddress((void**)&pcos, g_cosf);
    cudaGetSymbolAddress((void**)&pw,   g_w);
    cudaGetSymbolAddress((void**)&pbqkv, g_bqkv);

    __half* hw = (__half*)pw;
    __half* hWqkv = hw;                        // [3072][1024] = 3M halves
    __half* hWo   = hw + 3*1048576;            // [1024][1024] = 1M
    __half* hW1   = hw + 4*1048576;            // [4096][1024] = 4M
    __half* hW2   = hw + 8*1048576;            // [1024][4096] = 4M

    cudaFuncSetAttribute(attn_mma_kernel,
                         cudaFuncAttributeMaxDynamicSharedMemorySize, ATTN_SMEM);
    cudaFuncSetAttribute(hgemm,
                         cudaFuncAttributeMaxDynamicSharedMemorySize, GEMM_SMEM);

    // 0. weight transpose+convert to fp16 [N][K]
    dim3 tb(32, 8);
    cvtw_t_kernel<<<dim3(32, 32),  tb>>>(Wq, hWqkv,              1024, 1024);
    cvtw_t_kernel<<<dim3(32, 32),  tb>>>(Wk, hWqkv + 1024*1024,  1024, 1024);
    cvtw_t_kernel<<<dim3(32, 32),  tb>>>(Wv, hWqkv + 2048*1024,  1024, 1024);
    cvtw_t_kernel<<<dim3(32, 32),  tb>>>(Wo, hWo,                1024, 1024);
    cvtw_t_kernel<<<dim3(128, 32), tb>>>(W1, hW1,                1024, 4096);
    cvtw_t_kernel<<<dim3(32, 128), tb>>>(W2, hW2,                4096, 1024);
    pack_bias_kernel<<<QKV_N/256, 256>>>(bq, bk, bv, pbqkv);

    // 1. RoPE factors
    rope_factors_kernel<<<TT, 256>>>(ropeA, ropeB, psin, pcos);

    // 2. fused QKV projection (fp16 tensor core)
    dim3 gqkv(QKV_N/128, MROWS/128);
    hgemm<<<gqkv, 128, GEMM_SMEM>>>(tgt, hWqkv, pbqkv, nullptr, pqkv,
                                    MROWS, QKV_N, D_MODEL, 0);

    // 3. RoPE on q, k (inside packed qkv)
    rope_apply_kernel<<<(MROWS*512)/256, 256>>>(pqkv, psin, pcos);

    // 4. Attention (tf32 tensor core)
    dim3 ga(TT/64, BB*N_HEADS);
    attn_mma_kernel<<<ga, 128, ATTN_SMEM>>>(pqkv, pqkv + 1024, pqkv + 2048,
                                            QKV_N, pctx);

    // 5. Output projection + residual
    dim3 g1024(D_MODEL/128, MROWS/128);
    hgemm<<<g1024, 128, GEMM_SMEM>>>(pctx, hWo, bo, tgt, px, MROWS, D_MODEL, D_MODEL, 0);

    // 6. LN1
    layernorm_kernel<<<MROWS, 256>>>(px, ln1g, ln1b, px1);

    // 7. FFN
    dim3 gff1(D_FF/128, MROWS/128);
    hgemm<<<gff1, 128, GEMM_SMEM>>>(px1, hW1, b1, nullptr, pff, MROWS, D_FF, D_MODEL, 1);
    hgemm<<<g1024, 128, GEMM_SMEM>>>(pff, hW2, b2, px1, px, MROWS, D_MODEL, D_FF, 0);

    // 8. LN2 -> output
    layernorm_kernel<<<MROWS, 256>>>(px, ln2g, ln2b, out);
}